// round 4
// baseline (speedup 1.0000x reference)
#include <cuda_runtime.h>
#include <cuda_bf16.h>

// SE block: B=32, H=W=56 (HW=3136), C=256, R=16
#define HW     3136
#define CCH    256
#define NB     32
#define NS     49              // hw chunks per batch
#define CHUNK  64              // hw rows per unit
#define NUNIT  (NB * NS)       // 1568 units, u = b*49 + s
#define NBLK   592             // 148 SMs * 4 (co-resident, but no grid barrier needed)

// Scratch (__device__ globals; zero-initialized at module load, self-resetting)
__device__ float g_partial[NUNIT * CCH];        // [u][c]
__device__ float g_gate[NB * CCH];
__device__ unsigned g_done[NB];                 // pool units completed per batch
__device__ unsigned g_used[NB];                 // scale units consumed per batch
__device__ volatile int g_ready[NB];            // gate published flag

__global__ void __launch_bounds__(256, 4)
k_se(const float* __restrict__ x,
     const float* __restrict__ w1,
     const float* __restrict__ b1,
     const float* __restrict__ w2,
     const float* __restrict__ b2,
     float* __restrict__ out) {
    const int bid = blockIdx.x;
    const int t   = threadIdx.x;
    const int c4  = t & 63;        // float4 channel group
    const int ho  = t >> 6;        // hw sub-offset 0..3

    const float4* x4 = reinterpret_cast<const float4*>(x);
    float4*       o4 = reinterpret_cast<float4*>(out);

    __shared__ float4 sm[256];
    __shared__ int    s_flag;
    __shared__ int    s_w1_loaded;
    __shared__ float  s_s[CCH];
    __shared__ float  s_h[16];
    __shared__ float  s_w1[CCH * 16];

    if (t == 0) s_w1_loaded = 0;
    __syncthreads();

    // ---------------- Phase 1: pool, with inline MLP on batch completion ----------------
    for (int u = bid; u < NUNIT; u += NBLK) {
        const int b = u / NS, s = u - b * NS;
        const float4* xp = x4 + ((size_t)b * HW + (size_t)s * CHUNK + ho) * (CCH / 4) + c4;

        float4 acc = make_float4(0.f, 0.f, 0.f, 0.f);
#pragma unroll
        for (int k = 0; k < CHUNK; k += 4) {
            float4 v = xp[(size_t)k * (CCH / 4)];
            acc.x += v.x; acc.y += v.y; acc.z += v.z; acc.w += v.w;
        }
        sm[t] = acc;
        __syncthreads();
        if (t < 64) {
            float4 a = sm[t], e = sm[t + 64], f = sm[t + 128], h = sm[t + 192];
            float4 r = make_float4(a.x + e.x + f.x + h.x,
                                   a.y + e.y + f.y + h.y,
                                   a.z + e.z + f.z + h.z,
                                   a.w + e.w + f.w + h.w);
            reinterpret_cast<float4*>(g_partial)[(size_t)u * (CCH / 4) + t] = r;
        }
        __threadfence();              // publish partials device-wide (all threads)
        __syncthreads();
        if (t == 0) {
            unsigned old = atomicAdd(&g_done[b], 1u);
            s_flag = (old == NS - 1);
        }
        __syncthreads();

        if (s_flag) {
            // This block completed batch b -> run its excitation MLP inline.
            if (!s_w1_loaded) {
#pragma unroll
                for (int i = t; i < CCH * 16; i += 256) s_w1[i] = w1[i];
            }
            float accm = 0.f;
#pragma unroll
            for (int ss = 0; ss < NS; ss++)
                accm += __ldcg(&g_partial[((size_t)b * NS + ss) * CCH + t]);
            s_s[t] = accm * (1.0f / (float)HW);
            __syncthreads();
            if (t == 0) s_w1_loaded = 1;

            if (t < 16) {
                float h = b1[t];
#pragma unroll 8
                for (int k = 0; k < CCH; k++)
                    h = fmaf(s_s[k], s_w1[k * 16 + t], h);
                s_h[t] = fmaxf(h, 0.f);
            }
            __syncthreads();

            float g = b2[t];
#pragma unroll
            for (int j = 0; j < 16; j++)
                g = fmaf(s_h[j], w2[j * CCH + t], g);
            g_gate[b * CCH + t] = 1.f / (1.f + __expf(-g));

            __threadfence();          // publish gate (all threads)
            __syncthreads();
            if (t == 0) g_ready[b] = 1;
            __syncthreads();
        }
    }

    // ---------------- Phase 2: broadcast multiply (pipelined against phase 1) ----------------
    // Forward order: earliest batches become ready first.
    int last_b = -1;
    float4 g = make_float4(0.f, 0.f, 0.f, 0.f);
    for (int u = bid; u < NUNIT; u += NBLK) {
        const int b = u / NS, s = u - b * NS;
        if (b != last_b) {
            if (t == 0) {
                while (!g_ready[b]) __nanosleep(64);
            }
            __syncthreads();
            last_b = b;
            const float4* gp = reinterpret_cast<const float4*>(g_gate) + b * (CCH / 4) + c4;
            g.x = __ldcg(&gp->x); g.y = __ldcg(&gp->y);
            g.z = __ldcg(&gp->z); g.w = __ldcg(&gp->w);
        }

        const size_t base = ((size_t)b * HW + (size_t)s * CHUNK + ho) * (CCH / 4) + c4;
#pragma unroll
        for (int k = 0; k < CHUNK; k += 4) {
            const size_t idx = base + (size_t)k * (CCH / 4);
            float4 v = x4[idx];
            v.x *= g.x; v.y *= g.y; v.z *= g.z; v.w *= g.w;
            __stcs(&o4[idx], v);
        }

        if (t == 0) {
            unsigned old = atomicAdd(&g_used[b], 1u);
            if (old == NS - 1) {      // last consumer: reset state for next graph replay
                g_used[b]  = 0;
                g_done[b]  = 0;
                g_ready[b] = 0;
            }
        }
    }
}

extern "C" void kernel_launch(void* const* d_in, const int* in_sizes, int n_in,
                              void* d_out, int out_size) {
    const float* x  = (const float*)d_in[0];
    const float* w1 = (const float*)d_in[1];
    const float* b1 = (const float*)d_in[2];
    const float* w2 = (const float*)d_in[3];
    const float* b2 = (const float*)d_in[4];
    float* out = (float*)d_out;

    k_se<<<NBLK, 256>>>(x, w1, b1, w2, b2, out);
}

// round 5
// speedup vs baseline: 1.1101x; 1.1101x over previous
#include <cuda_runtime.h>
#include <cuda_bf16.h>

// SE block: B=32, H=W=56 (HW=3136), C=256, R=16
#define HW     3136
#define CCH    256
#define NB     32
#define NS     49              // hw chunks (units) per batch
#define CHUNK  64              // hw rows per unit
#define NUNIT  (NB * NS)       // 1568 units, u = b*49 + s  (batch-major)
#define NPOOL  NUNIT           // pool blocks: bid 0..1567
#define NTOT   (2 * NUNIT)     // + scale blocks: bid 1568..3135

// Scratch (__device__ globals; zero-init at load; self-resetting each launch)
__device__ float g_partial[NUNIT * CCH];   // [u][c]
__device__ float g_gate[NB * CCH];
__device__ unsigned g_done[NB];            // pool units completed per batch
__device__ unsigned g_used[NB];            // scale units consumed per batch
__device__ volatile int g_ready[NB];       // gate-published flag

__global__ void __launch_bounds__(256)
k_se(const float* __restrict__ x,
     const float* __restrict__ w1,
     const float* __restrict__ b1,
     const float* __restrict__ w2,
     const float* __restrict__ b2,
     float* __restrict__ out) {
    const int bid = blockIdx.x;
    const int t   = threadIdx.x;
    const int c4  = t & 63;        // float4 channel group (0..63)
    const int ho  = t >> 6;        // hw sub-offset (0..3)

    const float4* x4 = reinterpret_cast<const float4*>(x);
    float4*       o4 = reinterpret_cast<float4*>(out);

    if (bid < NPOOL) {
        // ================= POOL block: one unit =================
        const int u = bid;                     // batch-major
        const int b = u / NS, s = u - b * NS;

        const float4* xp = x4 + ((size_t)b * HW + (size_t)s * CHUNK + ho) * (CCH / 4) + c4;
        float4 acc = make_float4(0.f, 0.f, 0.f, 0.f);
#pragma unroll
        for (int k = 0; k < CHUNK; k += 4) {
            float4 v = xp[(size_t)k * (CCH / 4)];
            acc.x += v.x; acc.y += v.y; acc.z += v.z; acc.w += v.w;
        }

        __shared__ float4 sm[256];
        __shared__ int s_flag;
        sm[t] = acc;
        __syncthreads();
        if (t < 64) {
            float4 a = sm[t], e = sm[t + 64], f = sm[t + 128], h = sm[t + 192];
            float4 r = make_float4(a.x + e.x + f.x + h.x,
                                   a.y + e.y + f.y + h.y,
                                   a.z + e.z + f.z + h.z,
                                   a.w + e.w + f.w + h.w);
            reinterpret_cast<float4*>(g_partial)[(size_t)u * (CCH / 4) + t] = r;
        }
        __threadfence();               // publish partials (threadFenceReduction pattern)
        __syncthreads();
        if (t == 0) {
            unsigned old = atomicAdd(&g_done[b], 1u);
            s_flag = (old == NS - 1);
        }
        __syncthreads();
        if (!s_flag) return;

        // ---- last pool block of batch b: excitation MLP ----
        __shared__ float s_s[CCH];
        __shared__ float s_h[16];
        __shared__ float s_w1[CCH * 16];
#pragma unroll
        for (int i = t; i < CCH * 16; i += 256) s_w1[i] = w1[i];

        float accm = 0.f;
#pragma unroll
        for (int ss = 0; ss < NS; ss++)
            accm += __ldcg(&g_partial[((size_t)b * NS + ss) * CCH + t]);
        s_s[t] = accm * (1.0f / (float)HW);
        __syncthreads();

        if (t < 16) {
            float h = b1[t];
#pragma unroll 8
            for (int k = 0; k < CCH; k++)
                h = fmaf(s_s[k], s_w1[k * 16 + t], h);
            s_h[t] = fmaxf(h, 0.f);
        }
        __syncthreads();

        float g = b2[t];
#pragma unroll
        for (int j = 0; j < 16; j++)
            g = fmaf(s_h[j], w2[j * CCH + t], g);
        g_gate[b * CCH + t] = 1.f / (1.f + __expf(-g));

        __threadfence();               // publish gate
        __syncthreads();
        if (t == 0) g_ready[b] = 1;
    } else {
        // ================= SCALE block: one unit =================
        const int u = bid - NPOOL;
        const int b = u / NS, s = u - b * NS;

        if (t == 0) {
            while (g_ready[b] == 0) __nanosleep(64);
        }
        __syncthreads();

        const float* gp = g_gate + b * CCH + 4 * c4;
        float4 g;
        g.x = __ldcg(gp + 0); g.y = __ldcg(gp + 1);
        g.z = __ldcg(gp + 2); g.w = __ldcg(gp + 3);

        const size_t base = ((size_t)b * HW + (size_t)s * CHUNK + ho) * (CCH / 4) + c4;
#pragma unroll
        for (int k = 0; k < CHUNK; k += 4) {
            const size_t idx = base + (size_t)k * (CCH / 4);
            float4 v = x4[idx];
            v.x *= g.x; v.y *= g.y; v.z *= g.z; v.w *= g.w;
            __stcs(&o4[idx], v);       // evict-first: don't pollute L2 with out
        }

        __threadfence();
        __syncthreads();
        if (t == 0) {
            unsigned old = atomicAdd(&g_used[b], 1u);
            if (old == NS - 1) {       // last consumer: reset for next graph replay
                g_used[b]  = 0;
                g_done[b]  = 0;
                g_ready[b] = 0;
            }
        }
    }
}

extern "C" void kernel_launch(void* const* d_in, const int* in_sizes, int n_in,
                              void* d_out, int out_size) {
    const float* x  = (const float*)d_in[0];
    const float* w1 = (const float*)d_in[1];
    const float* b1 = (const float*)d_in[2];
    const float* w2 = (const float*)d_in[3];
    const float* b2 = (const float*)d_in[4];
    float* out = (float*)d_out;

    k_se<<<NTOT, 256>>>(x, w1, b1, w2, b2, out);
}